// round 3
// baseline (speedup 1.0000x reference)
#include <cuda_runtime.h>
#include <cuda_bf16.h>

#define BATCH   8
#define NVERTS  468
#define NTRI    256
#define IMG     1024

// Per-(batch, sorted-triangle) edge data: 3 edges x float4(A, B, C, pad).
//   w_e(px,py) = A*px + B*py + C   (sign-compatible with the reference edge fn)
__device__ float4 g_coef[BATCH * NTRI * 3];

// One block per batch, 256 threads = 1 thread per triangle.
// Computes affine edge coefficients + triangle area, then rank-sorts by
// descending area (deterministic total order) and scatters to g_coef.
__global__ void prep_kernel(const float* __restrict__ lm,
                            const int* __restrict__ tri) {
    __shared__ float s_area[NTRI];

    const int b = blockIdx.x;
    const int t = threadIdx.x;

    const int i0 = tri[t * 3 + 0];
    const int i1 = tri[t * 3 + 1];
    const int i2 = tri[t * 3 + 2];

    const float* base = lm + (size_t)b * NVERTS * 3;
    const float ax = base[i0 * 3 + 0], ay = base[i0 * 3 + 1];
    const float bx = base[i1 * 3 + 0], by = base[i1 * 3 + 1];
    const float cx = base[i2 * 3 + 0], cy = base[i2 * 3 + 1];

    // edge(P,Q) at (px,py) = (Qx-Px)*(py-Py) - (Qy-Py)*(px-Px)
    //                      = -(Qy-Py)*px + (Qx-Px)*py + [(Qy-Py)*Px - (Qx-Px)*Py]
    // e0 = edge(b,c), e1 = edge(c,a), e2 = edge(a,b)
    float4 e0, e1, e2;
    {
        float dX = cx - bx, dY = cy - by;
        e0 = make_float4(-dY, dX, fmaf(dY, bx, -(dX * by)), 0.0f);
    }
    {
        float dX = ax - cx, dY = ay - cy;
        e1 = make_float4(-dY, dX, fmaf(dY, cx, -(dX * cy)), 0.0f);
    }
    {
        float dX = bx - ax, dY = by - ay;
        e2 = make_float4(-dY, dX, fmaf(dY, ax, -(dX * ay)), 0.0f);
    }

    // |2*area| as sort key
    const float area2 = fabsf((bx - ax) * (cy - ay) - (by - ay) * (cx - ax));
    s_area[t] = area2;
    __syncthreads();

    // Deterministic rank: descending area, ties broken by original index.
    int rank = 0;
    #pragma unroll 8
    for (int j = 0; j < NTRI; ++j) {
        const float aj = s_area[j];
        rank += (aj > area2) || (aj == area2 && j < t);
    }

    float4* o = g_coef + ((size_t)b * NTRI + rank) * 3;
    o[0] = e0;  o[1] = e1;  o[2] = e2;
}

// Tile = 32 (x) x 8 (y) pixels, 256 threads, 1 pixel/thread.
// Warp = one 32-pixel row: coalesced stores + coherent early exit.
// Coefs read via __ldg, warp-uniform broadcast, L1-resident after warmup.
__global__ __launch_bounds__(256)
void rast_kernel(float* __restrict__ out) {
    const int b = blockIdx.z;
    const float4* __restrict__ cf = g_coef + (size_t)b * NTRI * 3;

    const int x = blockIdx.x * 32 + (threadIdx.x & 31);
    const int y = blockIdx.y * 8  + (threadIdx.x >> 5);

    // Orthographic camera flips both axes: p = 1 - (idx + 0.5)/S
    const float px = 1.0f - ((float)x + 0.5f) * (1.0f / (float)IMG);
    const float py = 1.0f - ((float)y + 0.5f) * (1.0f / (float)IMG);

    unsigned int covered = 0u;

    #pragma unroll 1
    for (int t = 0; t < NTRI; t += 2) {
        // iter t
        {
            const float4 e0 = __ldg(cf + t * 3 + 0);
            const float4 e1 = __ldg(cf + t * 3 + 1);
            const float4 e2 = __ldg(cf + t * 3 + 2);
            const float w0 = fmaf(e0.x, px, fmaf(e0.y, py, e0.z));
            const float w1 = fmaf(e1.x, px, fmaf(e1.y, py, e1.z));
            const float w2 = fmaf(e2.x, px, fmaf(e2.y, py, e2.z));
            const float mn = fminf(w0, fminf(w1, w2));
            const float mx = fmaxf(w0, fmaxf(w1, w2));
            covered |= (mn >= 0.0f) | (mx <= 0.0f);
        }
        // iter t+1
        {
            const float4 e0 = __ldg(cf + t * 3 + 3);
            const float4 e1 = __ldg(cf + t * 3 + 4);
            const float4 e2 = __ldg(cf + t * 3 + 5);
            const float w0 = fmaf(e0.x, px, fmaf(e0.y, py, e0.z));
            const float w1 = fmaf(e1.x, px, fmaf(e1.y, py, e1.z));
            const float w2 = fmaf(e2.x, px, fmaf(e2.y, py, e2.z));
            const float mn = fminf(w0, fminf(w1, w2));
            const float mx = fmaxf(w0, fmaxf(w1, w2));
            covered |= (mn >= 0.0f) | (mx <= 0.0f);
        }
        if (__all_sync(0xffffffffu, covered)) break;
    }

    out[((size_t)b << 20) + (size_t)y * IMG + x] = covered ? 1.0f : 0.0f;
}

extern "C" void kernel_launch(void* const* d_in, const int* in_sizes, int n_in,
                              void* d_out, int out_size) {
    const float* landmarks = (const float*)d_in[0];   // [8, 468, 3] f32
    const int*   tri       = (const int*)d_in[1];     // [256, 3] i32
    float* out = (float*)d_out;                       // [8, 1024, 1024] -> f32

    prep_kernel<<<BATCH, NTRI>>>(landmarks, tri);

    dim3 grid(IMG / 32, IMG / 8, BATCH);
    rast_kernel<<<grid, 256>>>(out);
}

// round 4
// speedup vs baseline: 5.6804x; 5.6804x over previous
#include <cuda_runtime.h>
#include <cuda_bf16.h>

#define BATCH    8
#define NVERTS   468
#define NTRI     256
#define IMG      1024
#define TILES_X  32      // tile = 32 px wide
#define TILES_Y  128     // tile = 8 px tall
#define NTILES   (TILES_X * TILES_Y)

// Per-(batch, area-rank) affine edge coefs: 3 x float4(A, B, C, pad)
//   w_e(px,py) = A*px + B*py + C
__device__ float4        g_coef[BATCH * NTRI * 3];
// Per-(batch, area-rank) bbox in p-coords: (xmin, xmax, ymin, ymax)
__device__ float4        g_bbox[BATCH * NTRI];
// Per-(batch, tile) triangle lists (area-rank order) + counts
__device__ unsigned char g_list[BATCH * NTILES * NTRI];
__device__ int           g_cnt [BATCH * NTILES];

// ---------------------------------------------------------------- prep ----
__global__ void prep_kernel(const float* __restrict__ lm,
                            const int* __restrict__ tri) {
    __shared__ float s_area[NTRI];

    const int b = blockIdx.x;
    const int t = threadIdx.x;

    const int i0 = tri[t * 3 + 0];
    const int i1 = tri[t * 3 + 1];
    const int i2 = tri[t * 3 + 2];

    const float* base = lm + (size_t)b * NVERTS * 3;
    const float ax = base[i0 * 3 + 0], ay = base[i0 * 3 + 1];
    const float bx = base[i1 * 3 + 0], by = base[i1 * 3 + 1];
    const float cx = base[i2 * 3 + 0], cy = base[i2 * 3 + 1];

    // edge(P,Q)(px,py) = (Qx-Px)*(py-Py) - (Qy-Py)*(px-Px)
    //                  = -(Qy-Py)*px + (Qx-Px)*py + [(Qy-Py)*Px - (Qx-Px)*Py]
    float4 e0, e1, e2;
    { float dX = cx - bx, dY = cy - by;
      e0 = make_float4(-dY, dX, fmaf(dY, bx, -(dX * by)), 0.0f); }
    { float dX = ax - cx, dY = ay - cy;
      e1 = make_float4(-dY, dX, fmaf(dY, cx, -(dX * cy)), 0.0f); }
    { float dX = bx - ax, dY = by - ay;
      e2 = make_float4(-dY, dX, fmaf(dY, ax, -(dX * ay)), 0.0f); }

    const float area2 = fabsf((bx - ax) * (cy - ay) - (by - ay) * (cx - ax));
    s_area[t] = area2;
    __syncthreads();

    // Deterministic rank: descending area, ties by original index.
    int rank = 0;
    #pragma unroll 8
    for (int j = 0; j < NTRI; ++j) {
        const float aj = s_area[j];
        rank += (aj > area2) || (aj == area2 && j < t);
    }

    float4* o = g_coef + ((size_t)b * NTRI + rank) * 3;
    o[0] = e0;  o[1] = e1;  o[2] = e2;

    const float xmn = fminf(ax, fminf(bx, cx));
    const float xmx = fmaxf(ax, fmaxf(bx, cx));
    const float ymn = fminf(ay, fminf(by, cy));
    const float ymx = fmaxf(ay, fmaxf(by, cy));
    g_bbox[(size_t)b * NTRI + rank] = make_float4(xmn, xmx, ymn, ymx);
}

// ----------------------------------------------------------------- bin ----
// One block per (tile, batch); thread t tests area-rank-t triangle's bbox
// against the tile's p-range, compacts hits in rank order.
__global__ __launch_bounds__(256)
void bin_kernel() {
    __shared__ int s_woff[8];

    const int b  = blockIdx.z;
    const int tx = blockIdx.x;              // tile x: 32-px columns
    const int ty = blockIdx.y;              // tile y: 8-px rows
    const int t  = threadIdx.x;
    const int tile = ty * TILES_X + tx;

    // p = 1 - (idx + 0.5)/IMG  (both axes flipped) -> p-range of this tile
    const float pxmin = 1.0f - ((float)(tx * 32) + 31.5f) * (1.0f / IMG);
    const float pxmax = 1.0f - ((float)(tx * 32) + 0.5f)  * (1.0f / IMG);
    const float pymin = 1.0f - ((float)(ty * 8)  + 7.5f)  * (1.0f / IMG);
    const float pymax = 1.0f - ((float)(ty * 8)  + 0.5f)  * (1.0f / IMG);

    const float4 bb = g_bbox[(size_t)b * NTRI + t];  // xmin,xmax,ymin,ymax
    const bool hit = (bb.x <= pxmax) && (bb.y >= pxmin) &&
                     (bb.z <= pymax) && (bb.w >= pymin);

    const unsigned m   = __ballot_sync(0xffffffffu, hit);
    const int      wid = t >> 5, lid = t & 31;
    if (lid == 0) s_woff[wid] = __popc(m);
    __syncthreads();
    if (t == 0) {
        int s = 0;
        #pragma unroll
        for (int i = 0; i < 8; ++i) { int c = s_woff[i]; s_woff[i] = s; s += c; }
        g_cnt[(size_t)b * NTILES + tile] = s;
    }
    __syncthreads();

    if (hit) {
        const int pos = s_woff[wid] + __popc(m & ((1u << lid) - 1u));
        g_list[((size_t)b * NTILES + tile) * NTRI + pos] = (unsigned char)t;
    }
}

// ---------------------------------------------------------------- rast ----
// Block = 32x8 px tile, 256 threads, warp = one 32-px row.
__global__ __launch_bounds__(256)
void rast_kernel(float* __restrict__ out) {
    __shared__ unsigned char s_list[NTRI];
    __shared__ int s_cnt;

    const int b    = blockIdx.z;
    const int tile = blockIdx.y * TILES_X + blockIdx.x;

    if (threadIdx.x == 0) s_cnt = g_cnt[(size_t)b * NTILES + tile];
    // Stage full 256-byte list (only cnt valid; rest harmless).
    if (threadIdx.x < 64) {
        const uint4* src = reinterpret_cast<const uint4*>(
            g_list + ((size_t)b * NTILES + tile) * NTRI);
        reinterpret_cast<uint4*>(s_list)[threadIdx.x & 15] =
            (threadIdx.x < 16) ? src[threadIdx.x] : src[threadIdx.x & 15];
    }
    __syncthreads();
    const int cnt = s_cnt;

    const int x = blockIdx.x * 32 + (threadIdx.x & 31);
    const int y = blockIdx.y * 8  + (threadIdx.x >> 5);

    const float px = 1.0f - ((float)x + 0.5f) * (1.0f / IMG);
    const float py = 1.0f - ((float)y + 0.5f) * (1.0f / IMG);

    const float4* __restrict__ cf = g_coef + (size_t)b * NTRI * 3;

    unsigned int covered = 0u;

    #pragma unroll 1
    for (int t = 0; t < cnt; ++t) {
        const int e = s_list[t];
        const float4 e0 = __ldg(cf + e * 3 + 0);
        const float4 e1 = __ldg(cf + e * 3 + 1);
        const float4 e2 = __ldg(cf + e * 3 + 2);
        const float w0 = fmaf(e0.x, px, fmaf(e0.y, py, e0.z));
        const float w1 = fmaf(e1.x, px, fmaf(e1.y, py, e1.z));
        const float w2 = fmaf(e2.x, px, fmaf(e2.y, py, e2.z));
        const float mn = fminf(w0, fminf(w1, w2));
        const float mx = fmaxf(w0, fmaxf(w1, w2));
        covered |= (mn >= 0.0f) | (mx <= 0.0f);
        if (__all_sync(0xffffffffu, covered)) break;
    }

    out[((size_t)b << 20) + (size_t)y * IMG + x] = covered ? 1.0f : 0.0f;
}

// -------------------------------------------------------------- launch ----
extern "C" void kernel_launch(void* const* d_in, const int* in_sizes, int n_in,
                              void* d_out, int out_size) {
    const float* landmarks = (const float*)d_in[0];   // [8, 468, 3] f32
    const int*   tri       = (const int*)d_in[1];     // [256, 3] i32
    float* out = (float*)d_out;                       // [8, 1024, 1024] f32

    prep_kernel<<<BATCH, NTRI>>>(landmarks, tri);

    dim3 bgrid(TILES_X, TILES_Y, BATCH);
    bin_kernel<<<bgrid, 256>>>();

    dim3 rgrid(TILES_X, TILES_Y, BATCH);
    rast_kernel<<<rgrid, 256>>>(out);
}

// round 5
// speedup vs baseline: 10.5056x; 1.8494x over previous
#include <cuda_runtime.h>
#include <cuda_bf16.h>

#define BATCH    8
#define NVERTS   468
#define NTRI     256
#define IMG      1024
#define TILE_W   32
#define TILE_H   16
#define TILES_X  (IMG / TILE_W)    // 32
#define TILES_Y  (IMG / TILE_H)    // 64
#define NTILES   (TILES_X * TILES_Y)
#define FULL_EPS 1e-5f

// Per-(batch, area-rank) affine edge coefs: 3 x float4(A, B, C, pad)
//   w_e(px,py) = A*px + B*py + C
__device__ float4        g_coef[BATCH * NTRI * 3];
// Per-(batch, area-rank) bbox in p-coords: (xmin, xmax, ymin, ymax)
__device__ float4        g_bbox[BATCH * NTRI];
// Per-(batch, tile) triangle lists (area-rank order) + counts (-1 = tile full)
__device__ unsigned char g_list[BATCH * NTILES * NTRI];
__device__ int           g_cnt [BATCH * NTILES];

// ---------------------------------------------------------------- prep ----
__global__ void prep_kernel(const float* __restrict__ lm,
                            const int* __restrict__ tri) {
    __shared__ float s_area[NTRI];

    const int b = blockIdx.x;
    const int t = threadIdx.x;

    const int i0 = tri[t * 3 + 0];
    const int i1 = tri[t * 3 + 1];
    const int i2 = tri[t * 3 + 2];

    const float* base = lm + (size_t)b * NVERTS * 3;
    const float ax = base[i0 * 3 + 0], ay = base[i0 * 3 + 1];
    const float bx = base[i1 * 3 + 0], by = base[i1 * 3 + 1];
    const float cx = base[i2 * 3 + 0], cy = base[i2 * 3 + 1];

    // edge(P,Q)(px,py) = (Qx-Px)*(py-Py) - (Qy-Py)*(px-Px)
    //                  = -(Qy-Py)*px + (Qx-Px)*py + [(Qy-Py)*Px - (Qx-Px)*Py]
    float4 e0, e1, e2;
    { float dX = cx - bx, dY = cy - by;
      e0 = make_float4(-dY, dX, fmaf(dY, bx, -(dX * by)), 0.0f); }
    { float dX = ax - cx, dY = ay - cy;
      e1 = make_float4(-dY, dX, fmaf(dY, cx, -(dX * cy)), 0.0f); }
    { float dX = bx - ax, dY = by - ay;
      e2 = make_float4(-dY, dX, fmaf(dY, ax, -(dX * ay)), 0.0f); }

    const float area2 = fabsf((bx - ax) * (cy - ay) - (by - ay) * (cx - ax));
    s_area[t] = area2;
    __syncthreads();

    // Deterministic rank: descending area, ties by original index.
    int rank = 0;
    #pragma unroll 8
    for (int j = 0; j < NTRI; ++j) {
        const float aj = s_area[j];
        rank += (aj > area2) || (aj == area2 && j < t);
    }

    float4* o = g_coef + ((size_t)b * NTRI + rank) * 3;
    o[0] = e0;  o[1] = e1;  o[2] = e2;

    g_bbox[(size_t)b * NTRI + rank] = make_float4(
        fminf(ax, fminf(bx, cx)), fmaxf(ax, fmaxf(bx, cx)),
        fminf(ay, fminf(by, cy)), fmaxf(ay, fmaxf(by, cy)));
}

// ----------------------------------------------------------------- bin ----
// Block handles 4 vertically-stacked tiles of one (batch, tile-column).
// Thread t owns area-rank-t triangle; loads bbox + coefs once.
__global__ __launch_bounds__(256)
void bin_kernel() {
    __shared__ int s_woff[8];
    __shared__ int s_full;

    const int b   = blockIdx.z;
    const int tx  = blockIdx.x;             // tile column
    const int ty0 = blockIdx.y * 4;         // first of 4 tile rows
    const int t   = threadIdx.x;
    const int wid = t >> 5, lid = t & 31;

    const float4 bb = g_bbox[(size_t)b * NTRI + t];
    const float4 e0 = g_coef[((size_t)b * NTRI + t) * 3 + 0];
    const float4 e1 = g_coef[((size_t)b * NTRI + t) * 3 + 1];
    const float4 e2 = g_coef[((size_t)b * NTRI + t) * 3 + 2];

    // p = 1 - (idx + 0.5)/IMG : extreme pixel-center coords of the tile
    const float pxmin = 1.0f - ((float)(tx * TILE_W) + (TILE_W - 0.5f)) * (1.0f / IMG);
    const float pxmax = 1.0f - ((float)(tx * TILE_W) + 0.5f)            * (1.0f / IMG);

    #pragma unroll 1
    for (int tt = 0; tt < 4; ++tt) {
        const int ty = ty0 + tt;
        const float pymin = 1.0f - ((float)(ty * TILE_H) + (TILE_H - 0.5f)) * (1.0f / IMG);
        const float pymax = 1.0f - ((float)(ty * TILE_H) + 0.5f)            * (1.0f / IMG);

        const bool hit = (bb.x <= pxmax) && (bb.y >= pxmin) &&
                         (bb.z <= pymax) && (bb.w >= pymin);

        // Full-cover test: all 3 edge functions same-signed (with margin)
        // at all 4 extreme pixel centers -> every pixel center in tile inside.
        bool full = false;
        if (hit) {
            float mn =  1e30f, mx = -1e30f;
            #pragma unroll
            for (int c = 0; c < 4; ++c) {
                const float cx_ = (c & 1) ? pxmax : pxmin;
                const float cy_ = (c & 2) ? pymax : pymin;
                const float w0 = fmaf(e0.x, cx_, fmaf(e0.y, cy_, e0.z));
                const float w1 = fmaf(e1.x, cx_, fmaf(e1.y, cy_, e1.z));
                const float w2 = fmaf(e2.x, cx_, fmaf(e2.y, cy_, e2.z));
                mn = fminf(mn, fminf(w0, fminf(w1, w2)));
                mx = fmaxf(mx, fmaxf(w0, fmaxf(w1, w2)));
            }
            full = (mn >= FULL_EPS) || (mx <= -FULL_EPS);
        }

        if (t == 0) s_full = 0;
        __syncthreads();
        if (full) s_full = 1;                 // benign race (all write 1)
        const unsigned m = __ballot_sync(0xffffffffu, hit);
        if (lid == 0) s_woff[wid] = __popc(m);
        __syncthreads();

        const int tile = ty * TILES_X + tx;
        const int isfull = s_full;
        if (t == 0) {
            int s = 0;
            #pragma unroll
            for (int i = 0; i < 8; ++i) { int c = s_woff[i]; s_woff[i] = s; s += c; }
            g_cnt[(size_t)b * NTILES + tile] = isfull ? -1 : s;
        }
        __syncthreads();

        if (hit && !isfull) {
            const int pos = s_woff[wid] + __popc(m & ((1u << lid) - 1u));
            g_list[((size_t)b * NTILES + tile) * NTRI + pos] = (unsigned char)t;
        }
        __syncthreads();
    }
}

// ---------------------------------------------------------------- rast ----
// Block = 32x16 px tile, 256 threads, 2 px/thread (rows y and y+8).
// Warp = rows y, y+8 of a 32-px-wide strip.
__global__ __launch_bounds__(256)
void rast_kernel(float* __restrict__ out) {
    __shared__ unsigned char s_list[NTRI];
    __shared__ int s_cnt;

    const int b    = blockIdx.z;
    const int tile = blockIdx.y * TILES_X + blockIdx.x;

    if (threadIdx.x == 0) s_cnt = g_cnt[(size_t)b * NTILES + tile];
    if (threadIdx.x < 16) {
        const uint4* src = reinterpret_cast<const uint4*>(
            g_list + ((size_t)b * NTILES + tile) * NTRI);
        reinterpret_cast<uint4*>(s_list)[threadIdx.x] = src[threadIdx.x];
    }
    __syncthreads();
    const int cnt = s_cnt;

    const int x  = blockIdx.x * TILE_W + (threadIdx.x & 31);
    const int y0 = blockIdx.y * TILE_H + (threadIdx.x >> 5);
    const int y1 = y0 + 8;

    const size_t o0 = ((size_t)b << 20) + (size_t)y0 * IMG + x;
    const size_t o1 = ((size_t)b << 20) + (size_t)y1 * IMG + x;

    if (cnt < 0) {                  // tile fully covered by one triangle
        out[o0] = 1.0f;
        out[o1] = 1.0f;
        return;
    }

    const float px  = 1.0f - ((float)x  + 0.5f) * (1.0f / IMG);
    const float pya = 1.0f - ((float)y0 + 0.5f) * (1.0f / IMG);
    const float pyb = 1.0f - ((float)y1 + 0.5f) * (1.0f / IMG);

    const float4* __restrict__ cf = g_coef + (size_t)b * NTRI * 3;

    unsigned int ca = 0u, cb = 0u;

    #pragma unroll 1
    for (int t = 0; t < cnt; ++t) {
        const int e = s_list[t];
        const float4 e0 = __ldg(cf + e * 3 + 0);
        const float4 e1 = __ldg(cf + e * 3 + 1);
        const float4 e2 = __ldg(cf + e * 3 + 2);

        const float w0a = fmaf(e0.x, px, fmaf(e0.y, pya, e0.z));
        const float w1a = fmaf(e1.x, px, fmaf(e1.y, pya, e1.z));
        const float w2a = fmaf(e2.x, px, fmaf(e2.y, pya, e2.z));
        const float mna = fminf(w0a, fminf(w1a, w2a));
        const float mxa = fmaxf(w0a, fmaxf(w1a, w2a));
        ca |= (mna >= 0.0f) | (mxa <= 0.0f);

        const float w0b = fmaf(e0.x, px, fmaf(e0.y, pyb, e0.z));
        const float w1b = fmaf(e1.x, px, fmaf(e1.y, pyb, e1.z));
        const float w2b = fmaf(e2.x, px, fmaf(e2.y, pyb, e2.z));
        const float mnb = fminf(w0b, fminf(w1b, w2b));
        const float mxb = fmaxf(w0b, fmaxf(w1b, w2b));
        cb |= (mnb >= 0.0f) | (mxb <= 0.0f);

        if (__all_sync(0xffffffffu, ca & cb)) break;
    }

    out[o0] = ca ? 1.0f : 0.0f;
    out[o1] = cb ? 1.0f : 0.0f;
}

// -------------------------------------------------------------- launch ----
extern "C" void kernel_launch(void* const* d_in, const int* in_sizes, int n_in,
                              void* d_out, int out_size) {
    const float* landmarks = (const float*)d_in[0];   // [8, 468, 3] f32
    const int*   tri       = (const int*)d_in[1];     // [256, 3] i32
    float* out = (float*)d_out;                       // [8, 1024, 1024] f32

    prep_kernel<<<BATCH, NTRI>>>(landmarks, tri);

    dim3 bgrid(TILES_X, TILES_Y / 4, BATCH);
    bin_kernel<<<bgrid, 256>>>();

    dim3 rgrid(TILES_X, TILES_Y, BATCH);
    rast_kernel<<<rgrid, 256>>>(out);
}

// round 6
// speedup vs baseline: 12.1745x; 1.1589x over previous
#include <cuda_runtime.h>
#include <cuda_bf16.h>

#define BATCH    8
#define NVERTS   468
#define NTRI     256
#define IMG      1024
#define TILE_W   32
#define TILE_H   32
#define TILES_X  (IMG / TILE_W)    // 32
#define TILES_Y  (IMG / TILE_H)    // 32
#define NTILES   (TILES_X * TILES_Y)
#define FULL_EPS 1e-5f

// Per-(batch, area-rank) affine edge coefs: 3 x float4(A, B, C, pad)
//   w_e(px,py) = A*px + B*py + C
__device__ float4        g_coef[BATCH * NTRI * 3];
// Per-(batch, area-rank) bbox in p-coords: (xmin, xmax, ymin, ymax)
__device__ float4        g_bbox[BATCH * NTRI];
// Per-(batch, tile) triangle lists (area-rank order) + counts (-1 = tile full)
__device__ unsigned char g_list[BATCH * NTILES * NTRI];
__device__ int           g_cnt [BATCH * NTILES];

// ---------------------------------------------------------------- prep ----
__global__ void prep_kernel(const float* __restrict__ lm,
                            const int* __restrict__ tri) {
    __shared__ float s_area[NTRI];

    const int b = blockIdx.x;
    const int t = threadIdx.x;

    const int i0 = tri[t * 3 + 0];
    const int i1 = tri[t * 3 + 1];
    const int i2 = tri[t * 3 + 2];

    const float* base = lm + (size_t)b * NVERTS * 3;
    const float ax = base[i0 * 3 + 0], ay = base[i0 * 3 + 1];
    const float bx = base[i1 * 3 + 0], by = base[i1 * 3 + 1];
    const float cx = base[i2 * 3 + 0], cy = base[i2 * 3 + 1];

    // edge(P,Q)(px,py) = (Qx-Px)*(py-Py) - (Qy-Py)*(px-Px)
    //                  = -(Qy-Py)*px + (Qx-Px)*py + [(Qy-Py)*Px - (Qx-Px)*Py]
    float4 e0, e1, e2;
    { float dX = cx - bx, dY = cy - by;
      e0 = make_float4(-dY, dX, fmaf(dY, bx, -(dX * by)), 0.0f); }
    { float dX = ax - cx, dY = ay - cy;
      e1 = make_float4(-dY, dX, fmaf(dY, cx, -(dX * cy)), 0.0f); }
    { float dX = bx - ax, dY = by - ay;
      e2 = make_float4(-dY, dX, fmaf(dY, ax, -(dX * ay)), 0.0f); }

    const float area2 = fabsf((bx - ax) * (cy - ay) - (by - ay) * (cx - ax));
    s_area[t] = area2;
    __syncthreads();

    // Deterministic rank: descending area, ties by original index.
    // Vectorized LDS.128 over the area table.
    int rank = 0;
    const float4* sa4 = reinterpret_cast<const float4*>(s_area);
    #pragma unroll 4
    for (int j4 = 0; j4 < NTRI / 4; ++j4) {
        const float4 a = sa4[j4];
        const int j = j4 * 4;
        rank += (a.x > area2) || (a.x == area2 && (j + 0) < t);
        rank += (a.y > area2) || (a.y == area2 && (j + 1) < t);
        rank += (a.z > area2) || (a.z == area2 && (j + 2) < t);
        rank += (a.w > area2) || (a.w == area2 && (j + 3) < t);
    }

    float4* o = g_coef + ((size_t)b * NTRI + rank) * 3;
    o[0] = e0;  o[1] = e1;  o[2] = e2;

    g_bbox[(size_t)b * NTRI + rank] = make_float4(
        fminf(ax, fminf(bx, cx)), fmaxf(ax, fmaxf(bx, cx)),
        fminf(ay, fminf(by, cy)), fmaxf(ay, fmaxf(by, cy)));
}

// ----------------------------------------------------------------- bin ----
// Block handles 4 vertically-stacked 32x32 tiles of one (batch, tile-column).
// Thread t owns area-rank-t triangle; loads bbox + coefs once.
__global__ __launch_bounds__(256)
void bin_kernel() {
    __shared__ int s_woff[8];
    __shared__ int s_full;

    const int b   = blockIdx.z;
    const int tx  = blockIdx.x;             // tile column
    const int ty0 = blockIdx.y * 4;         // first of 4 tile rows
    const int t   = threadIdx.x;
    const int wid = t >> 5, lid = t & 31;

    const float4 bb = g_bbox[(size_t)b * NTRI + t];
    const float4 e0 = g_coef[((size_t)b * NTRI + t) * 3 + 0];
    const float4 e1 = g_coef[((size_t)b * NTRI + t) * 3 + 1];
    const float4 e2 = g_coef[((size_t)b * NTRI + t) * 3 + 2];

    // p = 1 - (idx + 0.5)/IMG : extreme pixel-center coords of the tile
    const float pxmin = 1.0f - ((float)(tx * TILE_W) + (TILE_W - 0.5f)) * (1.0f / IMG);
    const float pxmax = 1.0f - ((float)(tx * TILE_W) + 0.5f)            * (1.0f / IMG);

    #pragma unroll 1
    for (int tt = 0; tt < 4; ++tt) {
        const int ty = ty0 + tt;
        const float pymin = 1.0f - ((float)(ty * TILE_H) + (TILE_H - 0.5f)) * (1.0f / IMG);
        const float pymax = 1.0f - ((float)(ty * TILE_H) + 0.5f)            * (1.0f / IMG);

        const bool hit = (bb.x <= pxmax) && (bb.y >= pxmin) &&
                         (bb.z <= pymax) && (bb.w >= pymin);

        // Full-cover: all 3 edge fns same-signed (with margin) at all 4
        // extreme pixel centers -> every pixel center in the tile inside.
        bool full = false;
        if (hit) {
            float mn =  1e30f, mx = -1e30f;
            #pragma unroll
            for (int c = 0; c < 4; ++c) {
                const float cx_ = (c & 1) ? pxmax : pxmin;
                const float cy_ = (c & 2) ? pymax : pymin;
                const float w0 = fmaf(e0.x, cx_, fmaf(e0.y, cy_, e0.z));
                const float w1 = fmaf(e1.x, cx_, fmaf(e1.y, cy_, e1.z));
                const float w2 = fmaf(e2.x, cx_, fmaf(e2.y, cy_, e2.z));
                mn = fminf(mn, fminf(w0, fminf(w1, w2)));
                mx = fmaxf(mx, fmaxf(w0, fmaxf(w1, w2)));
            }
            full = (mn >= FULL_EPS) || (mx <= -FULL_EPS);
        }

        if (t == 0) s_full = 0;
        __syncthreads();
        if (full) s_full = 1;                 // benign race (all write 1)
        const unsigned m = __ballot_sync(0xffffffffu, hit);
        if (lid == 0) s_woff[wid] = __popc(m);
        __syncthreads();

        const int tile = ty * TILES_X + tx;
        const int isfull = s_full;
        if (t == 0) {
            int s = 0;
            #pragma unroll
            for (int i = 0; i < 8; ++i) { int c = s_woff[i]; s_woff[i] = s; s += c; }
            g_cnt[(size_t)b * NTILES + tile] = isfull ? -1 : s;
        }
        __syncthreads();

        if (hit && !isfull) {
            const int pos = s_woff[wid] + __popc(m & ((1u << lid) - 1u));
            g_list[((size_t)b * NTILES + tile) * NTRI + pos] = (unsigned char)t;
        }
        __syncthreads();
    }
}

// ---------------------------------------------------------------- rast ----
// Block = 32x32 px tile, 256 threads, 4 px/thread (rows y, y+8, y+16, y+24).
__global__ __launch_bounds__(256)
void rast_kernel(float* __restrict__ out) {
    __shared__ unsigned char s_list[NTRI];
    __shared__ int s_cnt;

    const int b    = blockIdx.z;
    const int tile = blockIdx.y * TILES_X + blockIdx.x;

    if (threadIdx.x == 0) s_cnt = g_cnt[(size_t)b * NTILES + tile];
    if (threadIdx.x < 16) {
        const uint4* src = reinterpret_cast<const uint4*>(
            g_list + ((size_t)b * NTILES + tile) * NTRI);
        reinterpret_cast<uint4*>(s_list)[threadIdx.x] = src[threadIdx.x];
    }
    __syncthreads();
    const int cnt = s_cnt;

    const int x  = blockIdx.x * TILE_W + (threadIdx.x & 31);
    const int y0 = blockIdx.y * TILE_H + (threadIdx.x >> 5);

    const size_t base = ((size_t)b << 20) + (size_t)y0 * IMG + x;
    const size_t o0 = base;
    const size_t o1 = base + 8  * IMG;
    const size_t o2 = base + 16 * IMG;
    const size_t o3 = base + 24 * IMG;

    if (cnt < 0) {                  // tile fully covered by one triangle
        out[o0] = 1.0f;  out[o1] = 1.0f;
        out[o2] = 1.0f;  out[o3] = 1.0f;
        return;
    }

    const float px  = 1.0f - ((float)x + 0.5f) * (1.0f / IMG);
    const float py0 = 1.0f - ((float)(y0)      + 0.5f) * (1.0f / IMG);
    const float py1 = 1.0f - ((float)(y0 + 8)  + 0.5f) * (1.0f / IMG);
    const float py2 = 1.0f - ((float)(y0 + 16) + 0.5f) * (1.0f / IMG);
    const float py3 = 1.0f - ((float)(y0 + 24) + 0.5f) * (1.0f / IMG);

    const float4* __restrict__ cf = g_coef + (size_t)b * NTRI * 3;

    unsigned int c0 = 0u, c1 = 0u, c2 = 0u, c3 = 0u;

    #pragma unroll 1
    for (int t = 0; t < cnt; ++t) {
        const int e = s_list[t];
        const float4 e0 = __ldg(cf + e * 3 + 0);
        const float4 e1 = __ldg(cf + e * 3 + 1);
        const float4 e2 = __ldg(cf + e * 3 + 2);

        // Row-invariant partial terms: u_e = A*px + C
        const float u0 = fmaf(e0.x, px, e0.z);
        const float u1 = fmaf(e1.x, px, e1.z);
        const float u2 = fmaf(e2.x, px, e2.z);

        {   const float w0 = fmaf(e0.y, py0, u0);
            const float w1 = fmaf(e1.y, py0, u1);
            const float w2 = fmaf(e2.y, py0, u2);
            const float mn = fminf(w0, fminf(w1, w2));
            const float mx = fmaxf(w0, fmaxf(w1, w2));
            c0 |= (mn >= 0.0f) | (mx <= 0.0f); }
        {   const float w0 = fmaf(e0.y, py1, u0);
            const float w1 = fmaf(e1.y, py1, u1);
            const float w2 = fmaf(e2.y, py1, u2);
            const float mn = fminf(w0, fminf(w1, w2));
            const float mx = fmaxf(w0, fmaxf(w1, w2));
            c1 |= (mn >= 0.0f) | (mx <= 0.0f); }
        {   const float w0 = fmaf(e0.y, py2, u0);
            const float w1 = fmaf(e1.y, py2, u1);
            const float w2 = fmaf(e2.y, py2, u2);
            const float mn = fminf(w0, fminf(w1, w2));
            const float mx = fmaxf(w0, fmaxf(w1, w2));
            c2 |= (mn >= 0.0f) | (mx <= 0.0f); }
        {   const float w0 = fmaf(e0.y, py3, u0);
            const float w1 = fmaf(e1.y, py3, u1);
            const float w2 = fmaf(e2.y, py3, u2);
            const float mn = fminf(w0, fminf(w1, w2));
            const float mx = fmaxf(w0, fmaxf(w1, w2));
            c3 |= (mn >= 0.0f) | (mx <= 0.0f); }

        if (__all_sync(0xffffffffu, c0 & c1 & c2 & c3)) break;
    }

    out[o0] = c0 ? 1.0f : 0.0f;
    out[o1] = c1 ? 1.0f : 0.0f;
    out[o2] = c2 ? 1.0f : 0.0f;
    out[o3] = c3 ? 1.0f : 0.0f;
}

// -------------------------------------------------------------- launch ----
extern "C" void kernel_launch(void* const* d_in, const int* in_sizes, int n_in,
                              void* d_out, int out_size) {
    const float* landmarks = (const float*)d_in[0];   // [8, 468, 3] f32
    const int*   tri       = (const int*)d_in[1];     // [256, 3] i32
    float* out = (float*)d_out;                       // [8, 1024, 1024] f32

    prep_kernel<<<BATCH, NTRI>>>(landmarks, tri);

    dim3 bgrid(TILES_X, TILES_Y / 4, BATCH);
    bin_kernel<<<bgrid, 256>>>();

    dim3 rgrid(TILES_X, TILES_Y, BATCH);
    rast_kernel<<<rgrid, 256>>>(out);
}

// round 7
// speedup vs baseline: 13.8211x; 1.1353x over previous
#include <cuda_runtime.h>
#include <cuda_bf16.h>

#define BATCH    8
#define NVERTS   468
#define NTRI     256
#define IMG      1024
#define TILE_W   32
#define TILE_H   32
#define TILES_X  (IMG / TILE_W)    // 32
#define TILES_Y  (IMG / TILE_H)    // 32
#define NTILES   (TILES_X * TILES_Y)
#define FULL_EPS 1e-5f
#define BIG_AREA2 0.2f             // 2*area threshold for "front of list" bucket

// Per-(batch, tri) affine edge coefs: 3 x float4(A, B, C, pad)
//   w_e(px,py) = A*px + B*py + C
__device__ float4        g_coef[BATCH * NTRI * 3];
// Per-(batch, tile) triangle lists (big-area-first order) + counts (-1 = full)
__device__ unsigned char g_list[BATCH * NTILES * NTRI];
__device__ int           g_cnt [BATCH * NTILES];

// ----------------------------------------------------------------- bin ----
// Block handles 4 vertically-stacked 32x32 tiles of one (batch, tile-column).
// Thread t owns triangle t: recomputes coefs/bbox from inputs (L1/L2-hot),
// removing the separate prep kernel. Blocks (x==0,y==0) persist coefs for rast.
__global__ __launch_bounds__(256)
void bin_kernel(const float* __restrict__ lm, const int* __restrict__ tri) {
    __shared__ int s_offA[8], s_offB[8];
    __shared__ int s_full;

    const int b   = blockIdx.z;
    const int tx  = blockIdx.x;             // tile column
    const int ty0 = blockIdx.y * 4;         // first of 4 tile rows
    const int t   = threadIdx.x;
    const int wid = t >> 5, lid = t & 31;

    const int i0 = tri[t * 3 + 0];
    const int i1 = tri[t * 3 + 1];
    const int i2 = tri[t * 3 + 2];
    const float* base = lm + (size_t)b * NVERTS * 3;
    const float ax = base[i0 * 3 + 0], ay = base[i0 * 3 + 1];
    const float bx = base[i1 * 3 + 0], by = base[i1 * 3 + 1];
    const float cx = base[i2 * 3 + 0], cy = base[i2 * 3 + 1];

    // edge(P,Q)(px,py) = (Qx-Px)*(py-Py) - (Qy-Py)*(px-Px)
    //                  = -(Qy-Py)*px + (Qx-Px)*py + [(Qy-Py)*Px - (Qx-Px)*Py]
    float4 e0, e1, e2;
    { float dX = cx - bx, dY = cy - by;
      e0 = make_float4(-dY, dX, fmaf(dY, bx, -(dX * by)), 0.0f); }
    { float dX = ax - cx, dY = ay - cy;
      e1 = make_float4(-dY, dX, fmaf(dY, cx, -(dX * cy)), 0.0f); }
    { float dX = bx - ax, dY = by - ay;
      e2 = make_float4(-dY, dX, fmaf(dY, ax, -(dX * ay)), 0.0f); }

    // Persist coefs once per batch for the rast kernel.
    if (tx == 0 && blockIdx.y == 0) {
        float4* o = g_coef + ((size_t)b * NTRI + t) * 3;
        o[0] = e0;  o[1] = e1;  o[2] = e2;
    }

    const float bxmn = fminf(ax, fminf(bx, cx));
    const float bxmx = fmaxf(ax, fmaxf(bx, cx));
    const float bymn = fminf(ay, fminf(by, cy));
    const float bymx = fmaxf(ay, fmaxf(by, cy));
    const float area2 = fabsf((bx - ax) * (cy - ay) - (by - ay) * (cx - ax));
    const bool  big   = area2 > BIG_AREA2;

    // p = 1 - (idx + 0.5)/IMG : extreme pixel-center coords of the tile
    const float pxmin = 1.0f - ((float)(tx * TILE_W) + (TILE_W - 0.5f)) * (1.0f / IMG);
    const float pxmax = 1.0f - ((float)(tx * TILE_W) + 0.5f)            * (1.0f / IMG);

    #pragma unroll 1
    for (int tt = 0; tt < 4; ++tt) {
        const int ty = ty0 + tt;
        const float pymin = 1.0f - ((float)(ty * TILE_H) + (TILE_H - 0.5f)) * (1.0f / IMG);
        const float pymax = 1.0f - ((float)(ty * TILE_H) + 0.5f)            * (1.0f / IMG);

        const bool hit = (bxmn <= pxmax) && (bxmx >= pxmin) &&
                         (bymn <= pymax) && (bymx >= pymin);

        // Full-cover: all 3 edge fns same-signed (with margin) at all 4
        // extreme pixel centers -> every pixel center in the tile inside.
        bool full = false;
        if (hit) {
            float mn =  1e30f, mx = -1e30f;
            #pragma unroll
            for (int c = 0; c < 4; ++c) {
                const float cx_ = (c & 1) ? pxmax : pxmin;
                const float cy_ = (c & 2) ? pymax : pymin;
                const float w0 = fmaf(e0.x, cx_, fmaf(e0.y, cy_, e0.z));
                const float w1 = fmaf(e1.x, cx_, fmaf(e1.y, cy_, e1.z));
                const float w2 = fmaf(e2.x, cx_, fmaf(e2.y, cy_, e2.z));
                mn = fminf(mn, fminf(w0, fminf(w1, w2)));
                mx = fmaxf(mx, fmaxf(w0, fmaxf(w1, w2)));
            }
            full = (mn >= FULL_EPS) || (mx <= -FULL_EPS);
        }

        if (t == 0) s_full = 0;
        __syncthreads();
        if (full) s_full = 1;                 // benign race (all write 1)
        const bool hA = hit && big;
        const bool hB = hit && !big;
        const unsigned mA = __ballot_sync(0xffffffffu, hA);
        const unsigned mB = __ballot_sync(0xffffffffu, hB);
        if (lid == 0) { s_offA[wid] = __popc(mA); s_offB[wid] = __popc(mB); }
        __syncthreads();

        const int tile = ty * TILES_X + tx;
        const int isfull = s_full;
        if (t == 0) {
            int s = 0;
            #pragma unroll
            for (int i = 0; i < 8; ++i) { int c = s_offA[i]; s_offA[i] = s; s += c; }
            #pragma unroll
            for (int i = 0; i < 8; ++i) { int c = s_offB[i]; s_offB[i] = s; s += c; }
            g_cnt[(size_t)b * NTILES + tile] = isfull ? -1 : s;
        }
        __syncthreads();

        if (!isfull) {
            unsigned char* lst = g_list + ((size_t)b * NTILES + tile) * NTRI;
            if (hA) lst[s_offA[wid] + __popc(mA & ((1u << lid) - 1u))] = (unsigned char)t;
            if (hB) lst[s_offB[wid] + __popc(mB & ((1u << lid) - 1u))] = (unsigned char)t;
        }
        __syncthreads();
    }
}

// ---------------------------------------------------------------- rast ----
// Block = 32x32 px tile, 256 threads, 4 px/thread (rows y, y+8, y+16, y+24).
// Compacted coefs staged to smem; inner loop is pure LDS broadcast.
__global__ __launch_bounds__(256)
void rast_kernel(float* __restrict__ out) {
    __shared__ float4 s_coef[NTRI][3];      // 12 KB (only cnt entries used)

    const int b    = blockIdx.z;
    const int tile = blockIdx.y * TILES_X + blockIdx.x;

    const int cnt = __ldg(&g_cnt[(size_t)b * NTILES + tile]);  // warp-uniform

    const int x  = blockIdx.x * TILE_W + (threadIdx.x & 31);
    const int y0 = blockIdx.y * TILE_H + (threadIdx.x >> 5);

    const size_t obase = ((size_t)b << 20) + (size_t)y0 * IMG + x;
    const size_t o0 = obase;
    const size_t o1 = obase + 8  * IMG;
    const size_t o2 = obase + 16 * IMG;
    const size_t o3 = obase + 24 * IMG;

    if (cnt < 0) {                  // tile fully covered by one triangle
        out[o0] = 1.0f;  out[o1] = 1.0f;
        out[o2] = 1.0f;  out[o3] = 1.0f;
        return;
    }

    // Stage compacted coefs: thread j gathers list slot j.
    if (threadIdx.x < cnt) {
        const int e = g_list[((size_t)b * NTILES + tile) * NTRI + threadIdx.x];
        const float4* __restrict__ cf = g_coef + ((size_t)b * NTRI + e) * 3;
        s_coef[threadIdx.x][0] = __ldg(cf + 0);
        s_coef[threadIdx.x][1] = __ldg(cf + 1);
        s_coef[threadIdx.x][2] = __ldg(cf + 2);
    }
    __syncthreads();

    const float px  = 1.0f - ((float)x + 0.5f) * (1.0f / IMG);
    const float py0 = 1.0f - ((float)(y0)      + 0.5f) * (1.0f / IMG);
    const float py1 = 1.0f - ((float)(y0 + 8)  + 0.5f) * (1.0f / IMG);
    const float py2 = 1.0f - ((float)(y0 + 16) + 0.5f) * (1.0f / IMG);
    const float py3 = 1.0f - ((float)(y0 + 24) + 0.5f) * (1.0f / IMG);

    unsigned int c0 = 0u, c1 = 0u, c2 = 0u, c3 = 0u;

    #pragma unroll 1
    for (int t = 0; t < cnt; ++t) {
        const float4 e0 = s_coef[t][0];
        const float4 e1 = s_coef[t][1];
        const float4 e2 = s_coef[t][2];

        // Row-invariant partial terms: u_e = A*px + C
        const float u0 = fmaf(e0.x, px, e0.z);
        const float u1 = fmaf(e1.x, px, e1.z);
        const float u2 = fmaf(e2.x, px, e2.z);

        {   const float w0 = fmaf(e0.y, py0, u0);
            const float w1 = fmaf(e1.y, py0, u1);
            const float w2 = fmaf(e2.y, py0, u2);
            const float mn = fminf(w0, fminf(w1, w2));
            const float mx = fmaxf(w0, fmaxf(w1, w2));
            c0 |= (mn >= 0.0f) | (mx <= 0.0f); }
        {   const float w0 = fmaf(e0.y, py1, u0);
            const float w1 = fmaf(e1.y, py1, u1);
            const float w2 = fmaf(e2.y, py1, u2);
            const float mn = fminf(w0, fminf(w1, w2));
            const float mx = fmaxf(w0, fmaxf(w1, w2));
            c1 |= (mn >= 0.0f) | (mx <= 0.0f); }
        {   const float w0 = fmaf(e0.y, py2, u0);
            const float w1 = fmaf(e1.y, py2, u1);
            const float w2 = fmaf(e2.y, py2, u2);
            const float mn = fminf(w0, fminf(w1, w2));
            const float mx = fmaxf(w0, fmaxf(w1, w2));
            c2 |= (mn >= 0.0f) | (mx <= 0.0f); }
        {   const float w0 = fmaf(e0.y, py3, u0);
            const float w1 = fmaf(e1.y, py3, u1);
            const float w2 = fmaf(e2.y, py3, u2);
            const float mn = fminf(w0, fminf(w1, w2));
            const float mx = fmaxf(w0, fmaxf(w1, w2));
            c3 |= (mn >= 0.0f) | (mx <= 0.0f); }

        if (__all_sync(0xffffffffu, c0 & c1 & c2 & c3)) break;
    }

    out[o0] = c0 ? 1.0f : 0.0f;
    out[o1] = c1 ? 1.0f : 0.0f;
    out[o2] = c2 ? 1.0f : 0.0f;
    out[o3] = c3 ? 1.0f : 0.0f;
}

// -------------------------------------------------------------- launch ----
extern "C" void kernel_launch(void* const* d_in, const int* in_sizes, int n_in,
                              void* d_out, int out_size) {
    const float* landmarks = (const float*)d_in[0];   // [8, 468, 3] f32
    const int*   tri       = (const int*)d_in[1];     // [256, 3] i32
    float* out = (float*)d_out;                       // [8, 1024, 1024] f32

    dim3 bgrid(TILES_X, TILES_Y / 4, BATCH);
    bin_kernel<<<bgrid, 256>>>(landmarks, tri);

    dim3 rgrid(TILES_X, TILES_Y, BATCH);
    rast_kernel<<<rgrid, 256>>>(out);
}

// round 8
// speedup vs baseline: 16.2045x; 1.1724x over previous
#include <cuda_runtime.h>
#include <cuda_bf16.h>

#define BATCH    8
#define NVERTS   468
#define NTRI     256
#define IMG      1024
#define TILE_W   32
#define TILE_H   32
#define TILES_X  (IMG / TILE_W)    // 32
#define TILES_Y  (IMG / TILE_H)    // 32
#define FULL_EPS 1e-5f
#define BIG_AREA2 0.2f             // 2*area threshold for "front of list" bucket

// --------------------------------------------------------------- fused ----
// One block per 32x32-pixel tile. Phase 1 (bin): thread t computes triangle
// t's affine edge coefs + bbox from the raw inputs, tests the tile, and
// ballot-compacts surviving coefs straight into shared memory (big-area
// triangles first). Phase 2 (rast): 4 px/thread over the compacted list,
// warp-coherent early exit, unrolled 2 triangles per vote.
__global__ __launch_bounds__(256)
void fused_kernel(const float* __restrict__ lm,
                  const int* __restrict__ tri,
                  float* __restrict__ out) {
    __shared__ float4 s_coef[NTRI][3];      // 12 KB, only s_cnt entries valid
    __shared__ int s_offA[8], s_offB[8];
    __shared__ int s_cnt;

    const int b   = blockIdx.z;
    const int t   = threadIdx.x;
    const int wid = t >> 5, lid = t & 31;

    // ---- Phase 1: per-triangle setup (thread t owns triangle t) ----
    const int i0 = tri[t * 3 + 0];
    const int i1 = tri[t * 3 + 1];
    const int i2 = tri[t * 3 + 2];
    const float* vbase = lm + (size_t)b * NVERTS * 3;
    const float ax = vbase[i0 * 3 + 0], ay = vbase[i0 * 3 + 1];
    const float bx = vbase[i1 * 3 + 0], by = vbase[i1 * 3 + 1];
    const float cx = vbase[i2 * 3 + 0], cy = vbase[i2 * 3 + 1];

    // edge(P,Q)(px,py) = (Qx-Px)*(py-Py) - (Qy-Py)*(px-Px)
    //                  = -(Qy-Py)*px + (Qx-Px)*py + [(Qy-Py)*Px - (Qx-Px)*Py]
    float4 e0, e1, e2;
    { float dX = cx - bx, dY = cy - by;
      e0 = make_float4(-dY, dX, fmaf(dY, bx, -(dX * by)), 0.0f); }
    { float dX = ax - cx, dY = ay - cy;
      e1 = make_float4(-dY, dX, fmaf(dY, cx, -(dX * cy)), 0.0f); }
    { float dX = bx - ax, dY = by - ay;
      e2 = make_float4(-dY, dX, fmaf(dY, ax, -(dX * ay)), 0.0f); }

    // Tile extreme pixel centers in p-space: p = 1 - (idx + 0.5)/IMG
    const float pxmin = 1.0f - ((float)(blockIdx.x * TILE_W) + (TILE_W - 0.5f)) * (1.0f / IMG);
    const float pxmax = 1.0f - ((float)(blockIdx.x * TILE_W) + 0.5f)            * (1.0f / IMG);
    const float pymin = 1.0f - ((float)(blockIdx.y * TILE_H) + (TILE_H - 0.5f)) * (1.0f / IMG);
    const float pymax = 1.0f - ((float)(blockIdx.y * TILE_H) + 0.5f)            * (1.0f / IMG);

    // Conservative bbox-vs-tile overlap
    const bool hit =
        (fminf(ax, fminf(bx, cx)) <= pxmax) && (fmaxf(ax, fmaxf(bx, cx)) >= pxmin) &&
        (fminf(ay, fminf(by, cy)) <= pymax) && (fmaxf(ay, fmaxf(by, cy)) >= pymin);

    // Full-cover: all 3 edge fns same-signed (with margin) at all 4 extreme
    // pixel centers -> every pixel center in the tile is inside.
    bool full = false;
    if (hit) {
        float mn =  1e30f, mx = -1e30f;
        #pragma unroll
        for (int c = 0; c < 4; ++c) {
            const float cx_ = (c & 1) ? pxmax : pxmin;
            const float cy_ = (c & 2) ? pymax : pymin;
            const float w0 = fmaf(e0.x, cx_, fmaf(e0.y, cy_, e0.z));
            const float w1 = fmaf(e1.x, cx_, fmaf(e1.y, cy_, e1.z));
            const float w2 = fmaf(e2.x, cx_, fmaf(e2.y, cy_, e2.z));
            mn = fminf(mn, fminf(w0, fminf(w1, w2)));
            mx = fmaxf(mx, fmaxf(w0, fmaxf(w1, w2)));
        }
        full = (mn >= FULL_EPS) || (mx <= -FULL_EPS);
    }

    const int x  = blockIdx.x * TILE_W + lid;
    const int y0 = blockIdx.y * TILE_H + wid;
    const size_t obase = ((size_t)b << 20) + (size_t)y0 * IMG + x;

    if (__syncthreads_or(full ? 1 : 0)) {   // tile fully covered
        out[obase]            = 1.0f;
        out[obase + 8  * IMG] = 1.0f;
        out[obase + 16 * IMG] = 1.0f;
        out[obase + 24 * IMG] = 1.0f;
        return;
    }

    // Two-bucket compaction: big-area triangles first (cover fastest).
    const float area2 = fabsf((bx - ax) * (cy - ay) - (by - ay) * (cx - ax));
    const bool hA = hit && (area2 > BIG_AREA2);
    const bool hB = hit && !(area2 > BIG_AREA2);
    const unsigned mA = __ballot_sync(0xffffffffu, hA);
    const unsigned mB = __ballot_sync(0xffffffffu, hB);
    if (lid == 0) { s_offA[wid] = __popc(mA); s_offB[wid] = __popc(mB); }
    __syncthreads();
    if (t == 0) {
        int s = 0;
        #pragma unroll
        for (int i = 0; i < 8; ++i) { int c = s_offA[i]; s_offA[i] = s; s += c; }
        #pragma unroll
        for (int i = 0; i < 8; ++i) { int c = s_offB[i]; s_offB[i] = s; s += c; }
        s_cnt = s;
    }
    __syncthreads();
    if (hA) {
        const int pos = s_offA[wid] + __popc(mA & ((1u << lid) - 1u));
        s_coef[pos][0] = e0;  s_coef[pos][1] = e1;  s_coef[pos][2] = e2;
    }
    if (hB) {
        const int pos = s_offB[wid] + __popc(mB & ((1u << lid) - 1u));
        s_coef[pos][0] = e0;  s_coef[pos][1] = e1;  s_coef[pos][2] = e2;
    }
    __syncthreads();
    const int cnt = s_cnt;

    // ---- Phase 2: rasterize 4 pixels/thread ----
    const float px  = 1.0f - ((float)x + 0.5f) * (1.0f / IMG);
    const float py0 = 1.0f - ((float)(y0)      + 0.5f) * (1.0f / IMG);
    const float py1 = 1.0f - ((float)(y0 + 8)  + 0.5f) * (1.0f / IMG);
    const float py2 = 1.0f - ((float)(y0 + 16) + 0.5f) * (1.0f / IMG);
    const float py3 = 1.0f - ((float)(y0 + 24) + 0.5f) * (1.0f / IMG);

    unsigned int c0 = 0u, c1 = 0u, c2 = 0u, c3 = 0u;

#define TRI_TEST(T)                                                          \
    {   const float4 f0 = s_coef[T][0];                                      \
        const float4 f1 = s_coef[T][1];                                      \
        const float4 f2 = s_coef[T][2];                                      \
        const float u0 = fmaf(f0.x, px, f0.z);                               \
        const float u1 = fmaf(f1.x, px, f1.z);                               \
        const float u2 = fmaf(f2.x, px, f2.z);                               \
        {   const float w0 = fmaf(f0.y, py0, u0);                            \
            const float w1 = fmaf(f1.y, py0, u1);                            \
            const float w2 = fmaf(f2.y, py0, u2);                            \
            const float mn = fminf(w0, fminf(w1, w2));                       \
            const float mx = fmaxf(w0, fmaxf(w1, w2));                       \
            c0 |= (mn >= 0.0f) | (mx <= 0.0f); }                             \
        {   const float w0 = fmaf(f0.y, py1, u0);                            \
            const float w1 = fmaf(f1.y, py1, u1);                            \
            const float w2 = fmaf(f2.y, py1, u2);                            \
            const float mn = fminf(w0, fminf(w1, w2));                       \
            const float mx = fmaxf(w0, fmaxf(w1, w2));                       \
            c1 |= (mn >= 0.0f) | (mx <= 0.0f); }                             \
        {   const float w0 = fmaf(f0.y, py2, u0);                            \
            const float w1 = fmaf(f1.y, py2, u1);                            \
            const float w2 = fmaf(f2.y, py2, u2);                            \
            const float mn = fminf(w0, fminf(w1, w2));                       \
            const float mx = fmaxf(w0, fmaxf(w1, w2));                       \
            c2 |= (mn >= 0.0f) | (mx <= 0.0f); }                             \
        {   const float w0 = fmaf(f0.y, py3, u0);                            \
            const float w1 = fmaf(f1.y, py3, u1);                            \
            const float w2 = fmaf(f2.y, py3, u2);                            \
            const float mn = fminf(w0, fminf(w1, w2));                       \
            const float mx = fmaxf(w0, fmaxf(w1, w2));                       \
            c3 |= (mn >= 0.0f) | (mx <= 0.0f); }                             \
    }

    int k = 0;
    #pragma unroll 1
    for (; k + 2 <= cnt; k += 2) {
        TRI_TEST(k)
        TRI_TEST(k + 1)
        if (__all_sync(0xffffffffu, c0 & c1 & c2 & c3)) break;
    }
    if (k + 1 == cnt) {       // odd remainder (only reached if no early exit)
        TRI_TEST(k)
    }
#undef TRI_TEST

    out[obase]            = c0 ? 1.0f : 0.0f;
    out[obase + 8  * IMG] = c1 ? 1.0f : 0.0f;
    out[obase + 16 * IMG] = c2 ? 1.0f : 0.0f;
    out[obase + 24 * IMG] = c3 ? 1.0f : 0.0f;
}

// -------------------------------------------------------------- launch ----
extern "C" void kernel_launch(void* const* d_in, const int* in_sizes, int n_in,
                              void* d_out, int out_size) {
    const float* landmarks = (const float*)d_in[0];   // [8, 468, 3] f32
    const int*   tri       = (const int*)d_in[1];     // [256, 3] i32
    float* out = (float*)d_out;                       // [8, 1024, 1024] f32

    dim3 grid(TILES_X, TILES_Y, BATCH);
    fused_kernel<<<grid, 256>>>(landmarks, tri, out);
}

// round 9
// speedup vs baseline: 17.1875x; 1.0607x over previous
#include <cuda_runtime.h>
#include <cuda_bf16.h>

#define BATCH    8
#define NVERTS   468
#define NTRI     256
#define IMG      1024
#define TILE_W   32
#define TILE_H   32
#define TILES_X  (IMG / TILE_W)    // 32
#define TILES_Y  (IMG / TILE_H)    // 32
#define FULL_EPS 1e-5f
#define BIG_AREA2 0.2f             // 2*area threshold for "front of list" bucket

#define LM_FLOATS   (NVERTS * 3)   // 1404 floats = 351 float4 (5616 B)
#define TRI_INTS    (NTRI * 3)     // 768 ints  = 192 int4   (3072 B)

// --------------------------------------------------------------- fused ----
// One block per 32x32-pixel tile.
// Phase 0: stage landmarks+tri into smem with coalesced vector loads
//          (overlaid on s_coef; barrier separates read/overwrite).
// Phase 1: thread t computes triangle t's affine edge coefs + bbox from
//          smem, tests bbox-vs-tile and tile-full-cover, ballot-compacts
//          surviving coefs into s_coef (big-area triangles first).
// Phase 2: 4 px/thread; coverage via sign-bit LOP3 accumulation; warp vote
//          every 2 triangles for early exit.
__global__ __launch_bounds__(256)
void fused_kernel(const float* __restrict__ lm,
                  const int* __restrict__ tri,
                  float* __restrict__ out) {
    __shared__ float4 s_coef[NTRI][3];      // 12 KB (staging overlays this)
    __shared__ int s_offA[8], s_offB[8];
    __shared__ int s_cnt;

    float* s_lmf  = reinterpret_cast<float*>(s_coef);               // 1404 f
    int*   s_trii = reinterpret_cast<int*>(
                        reinterpret_cast<char*>(s_coef) + LM_FLOATS * 4);

    const int b   = blockIdx.z;
    const int t   = threadIdx.x;
    const int wid = t >> 5, lid = t & 31;

    // ---- Phase 0: coalesced staging ----
    {
        const float4* src = reinterpret_cast<const float4*>(
            lm + (size_t)b * LM_FLOATS);                  // 5616 B, 16-aligned
        float4* dst = reinterpret_cast<float4*>(s_lmf);
        for (int i = t; i < LM_FLOATS / 4; i += 256) dst[i] = src[i];
        const int4* tsrc = reinterpret_cast<const int4*>(tri);
        int4* tdst = reinterpret_cast<int4*>(s_trii);
        for (int i = t; i < TRI_INTS / 4; i += 256) tdst[i] = tsrc[i];
    }
    __syncthreads();

    // ---- Phase 1: per-triangle setup from smem ----
    const int i0 = s_trii[t * 3 + 0];
    const int i1 = s_trii[t * 3 + 1];
    const int i2 = s_trii[t * 3 + 2];
    const float ax = s_lmf[i0 * 3 + 0], ay = s_lmf[i0 * 3 + 1];
    const float bx = s_lmf[i1 * 3 + 0], by = s_lmf[i1 * 3 + 1];
    const float cx = s_lmf[i2 * 3 + 0], cy = s_lmf[i2 * 3 + 1];

    // edge(P,Q)(px,py) = (Qx-Px)*(py-Py) - (Qy-Py)*(px-Px)
    //                  = -(Qy-Py)*px + (Qx-Px)*py + [(Qy-Py)*Px - (Qx-Px)*Py]
    float4 e0, e1, e2;
    { float dX = cx - bx, dY = cy - by;
      e0 = make_float4(-dY, dX, fmaf(dY, bx, -(dX * by)), 0.0f); }
    { float dX = ax - cx, dY = ay - cy;
      e1 = make_float4(-dY, dX, fmaf(dY, cx, -(dX * cy)), 0.0f); }
    { float dX = bx - ax, dY = by - ay;
      e2 = make_float4(-dY, dX, fmaf(dY, ax, -(dX * ay)), 0.0f); }

    // Tile extreme pixel centers in p-space: p = 1 - (idx + 0.5)/IMG
    const float pxmin = 1.0f - ((float)(blockIdx.x * TILE_W) + (TILE_W - 0.5f)) * (1.0f / IMG);
    const float pxmax = 1.0f - ((float)(blockIdx.x * TILE_W) + 0.5f)            * (1.0f / IMG);
    const float pymin = 1.0f - ((float)(blockIdx.y * TILE_H) + (TILE_H - 0.5f)) * (1.0f / IMG);
    const float pymax = 1.0f - ((float)(blockIdx.y * TILE_H) + 0.5f)            * (1.0f / IMG);

    const bool hit =
        (fminf(ax, fminf(bx, cx)) <= pxmax) && (fmaxf(ax, fmaxf(bx, cx)) >= pxmin) &&
        (fminf(ay, fminf(by, cy)) <= pymax) && (fmaxf(ay, fmaxf(by, cy)) >= pymin);

    // Full-cover: all 3 edge fns same-signed (with margin) at all 4 extreme
    // pixel centers -> every pixel center in the tile is inside.
    bool full = false;
    if (hit) {
        float mn =  1e30f, mx = -1e30f;
        #pragma unroll
        for (int c = 0; c < 4; ++c) {
            const float cx_ = (c & 1) ? pxmax : pxmin;
            const float cy_ = (c & 2) ? pymax : pymin;
            const float w0 = fmaf(e0.x, cx_, fmaf(e0.y, cy_, e0.z));
            const float w1 = fmaf(e1.x, cx_, fmaf(e1.y, cy_, e1.z));
            const float w2 = fmaf(e2.x, cx_, fmaf(e2.y, cy_, e2.z));
            mn = fminf(mn, fminf(w0, fminf(w1, w2)));
            mx = fmaxf(mx, fmaxf(w0, fmaxf(w1, w2)));
        }
        full = (mn >= FULL_EPS) || (mx <= -FULL_EPS);
    }

    const int x  = blockIdx.x * TILE_W + lid;
    const int y0 = blockIdx.y * TILE_H + wid;
    const size_t obase = ((size_t)b << 20) + (size_t)y0 * IMG + x;

    // Barrier: also fences staged-data reads before s_coef is overwritten.
    if (__syncthreads_or(full ? 1 : 0)) {   // tile fully covered
        out[obase]            = 1.0f;
        out[obase + 8  * IMG] = 1.0f;
        out[obase + 16 * IMG] = 1.0f;
        out[obase + 24 * IMG] = 1.0f;
        return;
    }

    // Two-bucket compaction: big-area triangles first (cover fastest).
    const float area2 = fabsf((bx - ax) * (cy - ay) - (by - ay) * (cx - ax));
    const bool hA = hit && (area2 > BIG_AREA2);
    const bool hB = hit && !(area2 > BIG_AREA2);
    const unsigned mA = __ballot_sync(0xffffffffu, hA);
    const unsigned mB = __ballot_sync(0xffffffffu, hB);
    if (lid == 0) { s_offA[wid] = __popc(mA); s_offB[wid] = __popc(mB); }
    __syncthreads();
    if (t == 0) {
        int s = 0;
        #pragma unroll
        for (int i = 0; i < 8; ++i) { int c = s_offA[i]; s_offA[i] = s; s += c; }
        #pragma unroll
        for (int i = 0; i < 8; ++i) { int c = s_offB[i]; s_offB[i] = s; s += c; }
        s_cnt = s;
    }
    __syncthreads();
    if (hA) {
        const int pos = s_offA[wid] + __popc(mA & ((1u << lid) - 1u));
        s_coef[pos][0] = e0;  s_coef[pos][1] = e1;  s_coef[pos][2] = e2;
    }
    if (hB) {
        const int pos = s_offB[wid] + __popc(mB & ((1u << lid) - 1u));
        s_coef[pos][0] = e0;  s_coef[pos][1] = e1;  s_coef[pos][2] = e2;
    }
    __syncthreads();
    const int cnt = s_cnt;

    // ---- Phase 2: rasterize 4 pixels/thread, sign-bit coverage ----
    const float px  = 1.0f - ((float)x + 0.5f) * (1.0f / IMG);
    const float py0 = 1.0f - ((float)(y0)      + 0.5f) * (1.0f / IMG);
    const float py1 = 1.0f - ((float)(y0 + 8)  + 0.5f) * (1.0f / IMG);
    const float py2 = 1.0f - ((float)(y0 + 16) + 0.5f) * (1.0f / IMG);
    const float py3 = 1.0f - ((float)(y0 + 24) + 0.5f) * (1.0f / IMG);

    // n_r sign bit: 1 = row-pixel not yet covered. Covered ⇔ n_r >= 0.
    // Per triangle: or3 = s0|s1|s2, an3 = s0&s1&s2 (sign bits of the 3 edge
    // fns); pixel covered by tri ⇔ not(or3<0 && an3>=0) ⇔ sign(or3 & ~an3)=0.
    int n0 = -1, n1 = -1, n2 = -1, n3 = -1;

#define TRI_TEST(T)                                                          \
    {   const float4 f0 = s_coef[T][0];                                      \
        const float4 f1 = s_coef[T][1];                                      \
        const float4 f2 = s_coef[T][2];                                      \
        const float u0 = fmaf(f0.x, px, f0.z);                               \
        const float u1 = fmaf(f1.x, px, f1.z);                               \
        const float u2 = fmaf(f2.x, px, f2.z);                               \
        {   const int a0 = __float_as_int(fmaf(f0.y, py0, u0));              \
            const int a1 = __float_as_int(fmaf(f1.y, py0, u1));              \
            const int a2 = __float_as_int(fmaf(f2.y, py0, u2));              \
            n0 &= (a0 | a1 | a2) & ~(a0 & a1 & a2); }                        \
        {   const int a0 = __float_as_int(fmaf(f0.y, py1, u0));              \
            const int a1 = __float_as_int(fmaf(f1.y, py1, u1));              \
            const int a2 = __float_as_int(fmaf(f2.y, py1, u2));              \
            n1 &= (a0 | a1 | a2) & ~(a0 & a1 & a2); }                        \
        {   const int a0 = __float_as_int(fmaf(f0.y, py2, u0));              \
            const int a1 = __float_as_int(fmaf(f1.y, py2, u1));              \
            const int a2 = __float_as_int(fmaf(f2.y, py2, u2));              \
            n2 &= (a0 | a1 | a2) & ~(a0 & a1 & a2); }                        \
        {   const int a0 = __float_as_int(fmaf(f0.y, py3, u0));              \
            const int a1 = __float_as_int(fmaf(f1.y, py3, u1));              \
            const int a2 = __float_as_int(fmaf(f2.y, py3, u2));              \
            n3 &= (a0 | a1 | a2) & ~(a0 & a1 & a2); }                        \
    }

    int k = 0;
    #pragma unroll 1
    for (; k + 2 <= cnt; k += 2) {
        TRI_TEST(k)
        TRI_TEST(k + 1)
        if (__all_sync(0xffffffffu, (n0 | n1 | n2 | n3) >= 0)) break;
    }
    if (k + 1 == cnt) {       // odd remainder (only reached if no early exit)
        TRI_TEST(k)
    }
#undef TRI_TEST

    out[obase]            = (n0 >= 0) ? 1.0f : 0.0f;
    out[obase + 8  * IMG] = (n1 >= 0) ? 1.0f : 0.0f;
    out[obase + 16 * IMG] = (n2 >= 0) ? 1.0f : 0.0f;
    out[obase + 24 * IMG] = (n3 >= 0) ? 1.0f : 0.0f;
}

// -------------------------------------------------------------- launch ----
extern "C" void kernel_launch(void* const* d_in, const int* in_sizes, int n_in,
                              void* d_out, int out_size) {
    const float* landmarks = (const float*)d_in[0];   // [8, 468, 3] f32
    const int*   tri       = (const int*)d_in[1];     // [256, 3] i32
    float* out = (float*)d_out;                       // [8, 1024, 1024] f32

    dim3 grid(TILES_X, TILES_Y, BATCH);
    fused_kernel<<<grid, 256>>>(landmarks, tri, out);
}